// round 9
// baseline (speedup 1.0000x reference)
#include <cuda_runtime.h>

#define HIDDEN   1024
#define SEQ      784
#define BATCH    512
#define NTHREADS 128
#define NWARPS   4
#define E        8                      // hidden states per thread
#define RING     8                      // ring depth (slots = t & 7)

// tanh from pre-scaled arg xvK = (2/ln2)*xv:  tanh = 1 - 2/(2^xvK + 1).
// Saturates safely at +-inf (ex2->Inf => rcp->0 => +1 ; ex2->0 => rcp(1)=1 => -1).
__device__ __forceinline__ float tanh_from_scaled(float xvK) {
    float e, rc;
    asm("ex2.approx.ftz.f32 %0, %1;" : "=f"(e) : "f"(xvK));
    asm("rcp.approx.ftz.f32 %0, %1;" : "=f"(rc) : "f"(e + 1.0f));
    return fmaf(-2.0f, rc, 1.0f);
}

__device__ __forceinline__ unsigned smem_u32(const void* p) {
    unsigned a;
    asm("{.reg .u64 t; cvta.to.shared.u64 t, %1; cvt.u32.u64 %0, t;}" : "=r"(a) : "l"(p));
    return a;
}
__device__ __forceinline__ unsigned lda_cta(unsigned a) {
    unsigned v;
    asm volatile("ld.acquire.cta.shared::cta.b32 %0, [%1];" : "=r"(v) : "r"(a) : "memory");
    return v;
}
__device__ __forceinline__ void str_cta(unsigned a, unsigned v) {
    asm volatile("st.release.cta.shared::cta.b32 [%0], %1;" :: "r"(a), "r"(v) : "memory");
}

// One block per batch element. HiPPO bilinear step collapses (A diagonal +
// rank-1 semiseparable) to ONE linear scan over hidden index i:
//   r_{i+1} = alf_i r_i + w_i,  w_i = gam_i h_i + dlt_i u      (r_0 = 0)
//   xv_i    = A1_i h_i + gam_i (c u - (c/2) r_i) ;  h_i = tanh(xv_i)
// Time-invariant multiplicative scan coefficients -> 'a' ladder precomputed;
// per step the warp scan runs on 'b' only.
// NO per-step __syncthreads: cross-warp flow is strictly lower->higher warp,
// done via a depth-8 (value, tag) ring with st.release / ld.acquire, plus
// lazy backpressure via per-warp done counters. Warps slip & pipeline freely.
// Deadlock-freedom: tag-waits point strictly down (higher warp waits on lower
// warp's already-enabled step); donev-waits only require progress within the
// ring slack. donev encodes consumed-through t' as t'+8 -> INIT donev = 7
// (t' = -1). (R7's donev=0 init was the startup deadlock.)
__global__ void __launch_bounds__(NTHREADS, 4)
ssm_scan_kernel(const float* __restrict__ x,
                const float* __restrict__ C,
                const float* __restrict__ W,
                const float* __restrict__ bias,
                float* __restrict__ out)
{
    __shared__ float    xs[SEQ];
    __shared__ float    wval[RING][NWARPS];
    __shared__ unsigned wtag[RING][NWARPS];   // tag = t+1 when wval[t&7][w] valid
    __shared__ unsigned donev[NWARPS];        // consumer progress: t'+8 (t' consumed)
    __shared__ float    wtot[NWARPS];
    __shared__ float    red[NWARPS];

    const int tid  = threadIdx.x;
    const int lane = tid & 31;
    const int wid  = tid >> 5;
    const int bidx = blockIdx.x;

    for (int i = tid; i < SEQ; i += NTHREADS) xs[i] = x[bidx * SEQ + i];
    if (tid < RING * NWARPS) ((unsigned*)wtag)[tid] = 0u;
    if (tid < NWARPS) donev[tid] = 7u;        // consumed-through = -1  (FIX)

    const unsigned tag_base  = smem_u32(&wtag[0][0]);
    const unsigned done_base = smem_u32(&donev[0]);

    const float KT = 2.885390081777927f;          // 2/ln(2)

    // ---- per-element constants, built in double (matches reference fp64 HiPPO) ----
    float alf[E], gam[E], dlt[E], A1K[E], Ks[E], h[E], w[E];
    float c_f, mc2K;
    {
        const double step = 1.0 / (double)SEQ;
        const double c    = 0.5 * step;
        c_f  = (float)c;
        mc2K = (float)(-0.5 * c) * KT;
        #pragma unroll
        for (int e = 0; e < E; ++e) {
            const double q = (double)(tid * E + e);
            const double P = sqrt(1.0 + 2.0 * q);
            const double D = 1.0 + c * (1.0 + q);
            alf[e] = (float)((1.0 - c * q) / D);
            gam[e] = (float)(2.0 * P / D);
            dlt[e] = (float)(step * P * P / D);
            A1K[e] = (float)((1.0 - c * (1.0 + q)) / D) * KT;
            h[e]   = 0.f;
        }
        float p = 1.f;
        #pragma unroll
        for (int e = E - 1; e >= 0; --e) { Ks[e] = p; p *= alf[e]; }
    }

    // ---- one-time 'a' ladder (time-invariant scan coefficients) ----
    float Athr = Ks[0] * alf[0];
    float saL[5];
    float sa = Athr;
    #pragma unroll
    for (int k = 0; k < 5; ++k) {
        saL[k] = sa;
        float ra = __shfl_up_sync(0xffffffffu, sa, 1 << k);
        if (lane >= (1 << k)) sa *= ra;
    }
    float eaC = __shfl_up_sync(0xffffffffu, sa, 1);
    if (lane == 0) eaC = 1.f;
    if (lane == 31) wtot[wid] = sa;
    __syncthreads();   // xs, tags, donev, wtot ready -- the ONLY pre-epilogue barrier

    // cw[w2] = prod_{w3=w2+1}^{wid-1} wtot[w3] for w2 < wid, else 0.
    float cw[NWARPS - 1];
    {
        float p = 1.f;
        #pragma unroll
        for (int w3 = NWARPS - 2; w3 >= 0; --w3) {
            if (w3 < wid) { cw[w3] = p; p *= wtot[w3]; }
            else           cw[w3] = 0.f;
        }
    }

    // =========================== main time loop ===========================
    #pragma unroll 8
    for (int t = 0; t < SEQ; ++t) {
        const int s = t & (RING - 1);

        // Lazy backpressure (producers 0..2, every 4 steps): before writing
        // steps t..t+3 (overwriting steps t-8..t-5), require every reader to
        // have consumed step >= t-5, i.e. donev >= (t-5)+8 = t+3.
        if ((t & 3) == 0 && wid < NWARPS - 1) {
            #pragma unroll
            for (int w2 = 1; w2 < NWARPS; ++w2)
                if (w2 > wid)
                    while ((int)lda_cta(done_base + 4u * w2) < t + 3) { }
        }

        const float u   = xs[t];
        const float cuK = (c_f * KT) * u;

        // ---- thread-local: w_e and cb = sum Ks_e * w_e (2-way tree) ----
        #pragma unroll
        for (int e = 0; e < E; ++e)
            w[e] = fmaf(gam[e], h[e], dlt[e] * u);
        float cb0 = 0.f, cb1 = 0.f;
        #pragma unroll
        for (int e = 0; e < E; e += 2) {
            cb0 = fmaf(Ks[e],     w[e],     cb0);
            cb1 = fmaf(Ks[e + 1], w[e + 1], cb1);
        }
        float sb = cb0 + cb1;

        // ---- warp inclusive scan on 'b' only ('a' ladder precomputed) ----
        #pragma unroll
        for (int k = 0; k < 5; ++k) {
            float rb = __shfl_up_sync(0xffffffffu, sb, 1 << k);
            if (lane >= (1 << k)) sb = fmaf(saL[k], rb, sb);
        }
        float eb = __shfl_up_sync(0xffffffffu, sb, 1);
        if (lane == 0) eb = 0.f;

        // publish warp total (warps 0..2; lane 31 holds the inclusive total)
        if (wid < NWARPS - 1 && lane == 31) {
            wval[s][wid] = sb;
            str_cta(tag_base + 4u * (unsigned)(s * NWARPS + wid), (unsigned)(t + 1));
        }

        // consume lower warps' totals (directional wait, no block barrier)
        float gb = 0.f;
        #pragma unroll
        for (int w2 = 0; w2 < NWARPS - 1; ++w2) {
            if (w2 < wid) {
                while (lda_cta(tag_base + 4u * (unsigned)(s * NWARPS + w2))
                       != (unsigned)(t + 1)) { }
                gb = fmaf(cw[w2], wval[s][w2], gb);
            }
        }
        float r = fmaf(eaC, gb, eb);   // r entering this thread's first element

        // publish consumption progress (readers 1..3, every 4 steps)
        if ((t & 3) == 3 && wid > 0 && lane == 0)
            str_cta(done_base + 4u * wid, (unsigned)(t + 8));

        // ---- apply: 1-FMA r-chain; xv/tanh hang off with full ILP ----
        #pragma unroll
        for (int e = 0; e < E; ++e) {
            float rhoK = fmaf(mc2K, r, cuK);
            float xv   = fmaf(gam[e], rhoK, A1K[e] * h[e]);
            r = fmaf(alf[e], r, w[e]);
            h[e] = tanh_from_scaled(xv);
        }
    }

    // ---- epilogue: y_b = C . h ; out[b][o] = y_b * W[o] + bias[o] ----
    float partial = 0.f;
    #pragma unroll
    for (int e = 0; e < E; ++e)
        partial = fmaf(__ldg(&C[tid * E + e]), h[e], partial);
    #pragma unroll
    for (int d = 16; d > 0; d >>= 1)
        partial += __shfl_down_sync(0xffffffffu, partial, d);
    if (lane == 0) red[wid] = partial;
    __syncthreads();
    if (tid == 0) {
        float y = (red[0] + red[1]) + (red[2] + red[3]);
        #pragma unroll
        for (int o = 0; o < 10; ++o)
            out[bidx * 10 + o] = fmaf(y, W[o], bias[o]);
    }
}

extern "C" void kernel_launch(void* const* d_in, const int* in_sizes, int n_in,
                              void* d_out, int out_size) {
    const float* x    = (const float*)d_in[0];   // (512, 784, 1)
    const float* C    = (const float*)d_in[1];   // (1, 1024)
    const float* W    = (const float*)d_in[2];   // (1, 10)
    const float* bias = (const float*)d_in[3];   // (10,)
    float* out        = (float*)d_out;           // (512, 10)
    ssm_scan_kernel<<<BATCH, NTHREADS>>>(x, C, W, bias, out);
}

// round 10
// speedup vs baseline: 1.4462x; 1.4462x over previous
#include <cuda_runtime.h>

#define HIDDEN   1024
#define SEQ      784
#define BATCH    512
#define NTHREADS 128
#define NWARPS   4
#define SPB      2                      // sequences per block, BOTH carried by EVERY warp
#define E        8                      // hidden states per thread per sequence

// tanh from pre-scaled arg xvK = (2/ln2)*xv:  tanh = 1 - 2/(2^xvK + 1).
// Saturates safely at +-inf (ex2->Inf => rcp->0 => +1 ; ex2->0 => rcp(1)=1 => -1).
__device__ __forceinline__ float tanh_from_scaled(float xvK) {
    float e, rc;
    asm("ex2.approx.ftz.f32 %0, %1;" : "=f"(e) : "f"(xvK));
    asm("rcp.approx.ftz.f32 %0, %1;" : "=f"(rc) : "f"(e + 1.0f));
    return fmaf(-2.0f, rc, 1.0f);
}

// One block serves TWO batch sequences; every warp processes the SAME hidden
// indices for both (constants shared), giving each warp two independent
// per-step dependency DAGs -> deterministic intra-warp latency hiding, and
// ONE barrier + ONE ladder pass per pair of sequence-steps.
//
// HiPPO bilinear step collapses (A diagonal + rank-1 semiseparable) to ONE
// linear scan over hidden index i:
//   r_{i+1} = alf_i r_i + w_i,  w_i = gam_i h_i + dlt_i u      (r_0 = 0)
//   xv_i    = A1_i h_i + gam_i (c u - (c/2) r_i) ;  h_i = tanh(xv_i)
// Time-invariant multiplicative scan coefficients -> 'a' ladder (saL, eaC,
// cw) precomputed once; per step the warp scan runs on 'b' only.
__global__ void __launch_bounds__(NTHREADS, 4)
ssm_scan_kernel(const float* __restrict__ x,
                const float* __restrict__ C,
                const float* __restrict__ W,
                const float* __restrict__ bias,
                float* __restrict__ out)
{
    __shared__ float  xsv[SEQ * SPB];    // interleaved: xsv[2t+s] = u of seq s at step t
    __shared__ float2 wtb[2][NWARPS];    // warp totals (b) for both seqs, parity-buffered
    __shared__ float  wtot[NWARPS];
    __shared__ float  red[NWARPS][SPB];

    const int tid  = threadIdx.x;
    const int lane = tid & 31;
    const int wid  = tid >> 5;
    const int bidx = blockIdx.x;

    // Stage both sequences, interleaving by step for a single LDS.64 per step.
    for (int i = tid; i < SPB * SEQ; i += NTHREADS) {
        const int s = i / SEQ, t = i - s * SEQ;
        xsv[2 * t + s] = x[(bidx * SPB + s) * SEQ + t];
    }

    const float KT = 2.885390081777927f;          // 2/ln(2)

    // ---- per-element constants, built in double (matches reference fp64 HiPPO);
    //      SHARED between the two sequences (same hidden indices). ----
    float alf[E], gam[E], dlt[E], A1K[E], Ks[E];
    float h0[E], h1[E], w0[E], w1[E];
    float c_f, mc2K;
    {
        const double step = 1.0 / (double)SEQ;
        const double c    = 0.5 * step;
        c_f  = (float)c;
        mc2K = (float)(-0.5 * c) * KT;
        #pragma unroll
        for (int e = 0; e < E; ++e) {
            const double q = (double)(tid * E + e);
            const double P = sqrt(1.0 + 2.0 * q);
            const double D = 1.0 + c * (1.0 + q);
            alf[e] = (float)((1.0 - c * q) / D);
            gam[e] = (float)(2.0 * P / D);
            dlt[e] = (float)(step * P * P / D);
            A1K[e] = (float)((1.0 - c * (1.0 + q)) / D) * KT;
            h0[e] = 0.f; h1[e] = 0.f;
        }
        float p = 1.f;
        #pragma unroll
        for (int e = E - 1; e >= 0; --e) { Ks[e] = p; p *= alf[e]; }
    }

    // ---- one-time 'a' ladder (time-invariant scan coefficients) ----
    float saL[5];
    float sa = Ks[0] * alf[0];
    #pragma unroll
    for (int k = 0; k < 5; ++k) {
        saL[k] = sa;
        float ra = __shfl_up_sync(0xffffffffu, sa, 1 << k);
        if (lane >= (1 << k)) sa *= ra;
    }
    float eaC = __shfl_up_sync(0xffffffffu, sa, 1);
    if (lane == 0) eaC = 1.f;
    if (lane == 31) wtot[wid] = sa;
    __syncthreads();

    // cw[w2] = prod_{w3=w2+1}^{wid-1} wtot[w3] for w2 < wid, else 0.
    float cw[NWARPS - 1];
    {
        float p = 1.f;
        #pragma unroll
        for (int w3 = NWARPS - 2; w3 >= 0; --w3) {
            if (w3 < wid) { cw[w3] = p; p *= wtot[w3]; }
            else           cw[w3] = 0.f;
        }
    }
    __syncthreads();

    // =========================== main time loop ===========================
    #pragma unroll 2
    for (int t = 0; t < SEQ; ++t) {
        const float2 uv  = *(const float2*)&xsv[2 * t];
        const float  u0  = uv.x,                u1  = uv.y;
        const float cuK0 = (c_f * KT) * u0;
        const float cuK1 = (c_f * KT) * u1;

        // ---- thread-local: w_e and cb = sum Ks_e * w_e (both streams) ----
        #pragma unroll
        for (int e = 0; e < E; ++e) {
            w0[e] = fmaf(gam[e], h0[e], dlt[e] * u0);
            w1[e] = fmaf(gam[e], h1[e], dlt[e] * u1);
        }
        float c0a = 0.f, c0b = 0.f, c1a = 0.f, c1b = 0.f;
        #pragma unroll
        for (int e = 0; e < E; e += 2) {
            c0a = fmaf(Ks[e],     w0[e],     c0a);
            c0b = fmaf(Ks[e + 1], w0[e + 1], c0b);
            c1a = fmaf(Ks[e],     w1[e],     c1a);
            c1b = fmaf(Ks[e + 1], w1[e + 1], c1b);
        }
        float sb0 = c0a + c0b;
        float sb1 = c1a + c1b;

        // ---- warp inclusive scan on 'b', two independent streams interleaved ----
        #pragma unroll
        for (int k = 0; k < 5; ++k) {
            float rb0 = __shfl_up_sync(0xffffffffu, sb0, 1 << k);
            float rb1 = __shfl_up_sync(0xffffffffu, sb1, 1 << k);
            if (lane >= (1 << k)) {
                sb0 = fmaf(saL[k], rb0, sb0);
                sb1 = fmaf(saL[k], rb1, sb1);
            }
        }
        float eb0 = __shfl_up_sync(0xffffffffu, sb0, 1);
        float eb1 = __shfl_up_sync(0xffffffffu, sb1, 1);
        if (lane == 0) { eb0 = 0.f; eb1 = 0.f; }

        const int par = t & 1;                       // constant under unroll 2
        if (lane == 31) wtb[par][wid] = make_float2(sb0, sb1);
        __syncthreads();            // ONE barrier advances BOTH sequences one step

        // cross-warp: constant-weighted sums (no chain), one LDS.64 per lower warp
        float gb0 = 0.f, gb1 = 0.f;
        #pragma unroll
        for (int w2 = 0; w2 < NWARPS - 1; ++w2) {
            if (w2 < wid) {
                const float2 v = wtb[par][w2];
                gb0 = fmaf(cw[w2], v.x, gb0);
                gb1 = fmaf(cw[w2], v.y, gb1);
            }
        }
        float r0 = fmaf(eaC, gb0, eb0);
        float r1 = fmaf(eaC, gb1, eb1);

        // ---- apply: two interleaved 1-FMA r-chains; xv/tanh off-chain ----
        #pragma unroll
        for (int e = 0; e < E; ++e) {
            float rho0 = fmaf(mc2K, r0, cuK0);
            float rho1 = fmaf(mc2K, r1, cuK1);
            float xv0  = fmaf(gam[e], rho0, A1K[e] * h0[e]);
            float xv1  = fmaf(gam[e], rho1, A1K[e] * h1[e]);
            r0 = fmaf(alf[e], r0, w0[e]);
            r1 = fmaf(alf[e], r1, w1[e]);
            h0[e] = tanh_from_scaled(xv0);
            h1[e] = tanh_from_scaled(xv1);
        }
    }

    // ---- epilogue: y_s = C . h_s ; out[bidx*2+s][o] = y_s*W[o] + bias[o] ----
    float p0 = 0.f, p1 = 0.f;
    #pragma unroll
    for (int e = 0; e < E; ++e) {
        const float Ce = __ldg(&C[tid * E + e]);
        p0 = fmaf(Ce, h0[e], p0);
        p1 = fmaf(Ce, h1[e], p1);
    }
    #pragma unroll
    for (int d = 16; d > 0; d >>= 1) {
        p0 += __shfl_down_sync(0xffffffffu, p0, d);
        p1 += __shfl_down_sync(0xffffffffu, p1, d);
    }
    if (lane == 0) { red[wid][0] = p0; red[wid][1] = p1; }
    __syncthreads();
    if (tid < SPB) {
        float y = (red[0][tid] + red[1][tid]) + (red[2][tid] + red[3][tid]);
        #pragma unroll
        for (int o = 0; o < 10; ++o)
            out[(bidx * SPB + tid) * 10 + o] = fmaf(y, W[o], bias[o]);
    }
}

extern "C" void kernel_launch(void* const* d_in, const int* in_sizes, int n_in,
                              void* d_out, int out_size) {
    const float* x    = (const float*)d_in[0];   // (512, 784, 1)
    const float* C    = (const float*)d_in[1];   // (1, 1024)
    const float* W    = (const float*)d_in[2];   // (1, 10)
    const float* bias = (const float*)d_in[3];   // (10,)
    float* out        = (float*)d_out;           // (512, 10)
    ssm_scan_kernel<<<BATCH / SPB, NTHREADS>>>(x, C, W, bias, out);
}